// round 16
// baseline (speedup 1.0000x reference)
#include <cuda_runtime.h>
#include <cuda_fp16.h>
#include <cstdint>

// x: [16,4096,384] fp32 -> out [16,4096,384] fp32
// 8x8 window attention over 64x64 grid, 12 heads, hd=32.
// fp16 1-term everywhere; 8-warp GEMM CTAs; 2-heads-per-block attention.

#define TOKENS   65536
#define C_DIM    384
#define QKV_DIM  1152

__device__ __half  g_qkv[(size_t)TOKENS * QKV_DIM];
__device__ __half  g_ao [(size_t)TOKENS * C_DIM];
__device__ __half  g_wq [(size_t)C_DIM * QKV_DIM];
__device__ __half  g_wp [(size_t)C_DIM * C_DIM];

static __device__ __forceinline__ uint32_t smem_u32(const void* p) {
    return (uint32_t)__cvta_generic_to_shared(p);
}

#define CP_ASYNC16(smem, gptr) \
    asm volatile("cp.async.cg.shared.global [%0], [%1], 16;" :: "r"(smem), "l"(gptr))
#define CP_COMMIT() asm volatile("cp.async.commit_group;" ::: "memory")

#define MMA_F16(d, a, b)                                                       \
    asm volatile(                                                              \
        "mma.sync.aligned.m16n8k16.row.col.f32.f16.f16.f32 "                   \
        "{%0,%1,%2,%3},{%4,%5,%6,%7},{%8,%9},{%0,%1,%2,%3};"                   \
        : "+f"(d[0]), "+f"(d[1]), "+f"(d[2]), "+f"(d[3])                       \
        : "r"(a[0]), "r"(a[1]), "r"(a[2]), "r"(a[3]), "r"(b[0]), "r"(b[1]))

// ---------------------------------------------------------------------------
// fp32 -> fp16 convert (weights)
// ---------------------------------------------------------------------------
__global__ void convert_kernel(const float* __restrict__ in,
                               __half* __restrict__ out16, int n4)
{
    int i = blockIdx.x * blockDim.x + threadIdx.x;
    if (i >= n4) return;
    float4 v = ((const float4*)in)[i];
    __half2* op = (__half2*)out16;
    op[i*2]   = __floats2half2_rn(v.x, v.y);
    op[i*2+1] = __floats2half2_rn(v.z, v.w);
}

// ---------------------------------------------------------------------------
// QKV GEMM (1-term, 256 threads / 8 warps 2x4, warp tile 64x32).
// A fp32 -> fp16 in-kernel; C = A16 @ W16 + bias; fp16 out (staged stores).
// smem: AF32 2x18432 @0 | AH 10240 @36864 | B 2x8704 @47104  (=64512)
// ---------------------------------------------------------------------------
#define FA_AF32    0
#define FA_AF32_ST 18432
#define FA_AH      36864
#define FA_B       47104
#define FA_B_ST    8704
#define FA_DYNSMEM 64512

__global__ __launch_bounds__(256, 2)
void gemm_qkv_kernel(const float* __restrict__ A,
                     const __half* __restrict__ B16,
                     const float* __restrict__ bias,
                     __half* __restrict__ C16, int N, int K)
{
    extern __shared__ char smem_raw[];
    const uint32_t sbase = smem_u32(smem_raw);

    const int tid  = threadIdx.x;
    const int lane = tid & 31;
    const int warp = tid >> 5;
    const int wm   = warp >> 2;     // 0..1
    const int wn   = warp & 3;      // 0..3
    const int m0   = blockIdx.y * 128;
    const int n0   = blockIdx.x * 128;
    const int KT   = K / 32;

    float acc[4][4][4];
    #pragma unroll
    for (int mi = 0; mi < 4; mi++)
        #pragma unroll
        for (int ni = 0; ni < 4; ni++)
            #pragma unroll
            for (int c = 0; c < 4; c++) acc[mi][ni][c] = 0.0f;

    // A fp32: 128 rows x 8 chunks = 1024 / 256 thr = 4 each
    uint32_t afo[4]; size_t afg[4];
    #pragma unroll
    for (int j = 0; j < 4; j++) {
        int idx = j * 256 + tid;
        int r = idx >> 3, c = idx & 7;
        afo[j] = (uint32_t)(r * 144 + c * 16);
        afg[j] = (size_t)r * K + c * 4;
    }
    // B fp16: 32 rows x 16 chunks = 512 / 256 = 2 each
    uint32_t bso[2]; size_t bgo[2];
    #pragma unroll
    for (int j = 0; j < 2; j++) {
        int idx = j * 256 + tid;
        int br = idx >> 4, bc = idx & 15;
        bso[j] = (uint32_t)(br * 272 + bc * 16);
        bgo[j] = (size_t)br * N + bc * 8;
    }

    auto load_stage = [&](int kt, int st) {
        uint32_t ab = sbase + FA_AF32 + st * FA_AF32_ST;
        const float* pa = A + (size_t)m0 * K + kt * 32;
        #pragma unroll
        for (int j = 0; j < 4; j++) CP_ASYNC16(ab + afo[j], pa + afg[j]);
        uint32_t bb = sbase + FA_B + st * FA_B_ST;
        const __half* pb = B16 + (size_t)(kt * 32) * N + n0;
        #pragma unroll
        for (int j = 0; j < 2; j++) CP_ASYNC16(bb + bso[j], pb + bgo[j]);
        CP_COMMIT();
    };

    load_stage(0, 0);

    for (int kt = 0; kt < KT; kt++) {
        const int st = kt & 1;
        asm volatile("cp.async.wait_group 0;" ::: "memory");
        __syncthreads();

        if (kt + 1 < KT) load_stage(kt + 1, st ^ 1);

        // Convert A fp32 -> fp16: thread handles half a row (16 floats)
        {
            const float* arow = (const float*)(smem_raw + FA_AF32 + st * FA_AF32_ST
                                               + (tid >> 1) * 144 + (tid & 1) * 64);
            __half* hrow = (__half*)(smem_raw + FA_AH + (tid >> 1) * 80 + (tid & 1) * 32);
            #pragma unroll
            for (int j = 0; j < 4; j++) {
                float4 v = *(const float4*)(arow + j * 4);
                *(__half2*)(hrow + j * 4)     = __floats2half2_rn(v.x, v.y);
                *(__half2*)(hrow + j * 4 + 2) = __floats2half2_rn(v.z, v.w);
            }
        }
        __syncthreads();

        const uint32_t bb = sbase + FA_B + st * FA_B_ST;
        #pragma unroll
        for (int kh = 0; kh < 2; kh++) {
            uint32_t bf[4][2];
            const int brow = kh * 16 + (lane & 15);
            #pragma unroll
            for (int ni = 0; ni < 4; ni++) {
                uint32_t ad = bb + brow * 272 + (uint32_t)((wn * 32 + ni * 8) * 2);
                asm volatile("ldmatrix.sync.aligned.m8n8.x2.trans.shared.b16 {%0,%1},[%2];"
                             : "=r"(bf[ni][0]), "=r"(bf[ni][1]) : "r"(ad));
            }
            #pragma unroll
            for (int mi = 0; mi < 4; mi++) {
                const int arow = wm * 64 + mi * 16 + ((lane >> 3) & 1) * 8 + (lane & 7);
                const int acol = kh * 16 + (lane >> 4) * 8;
                uint32_t Af[4];
                uint32_t ad = sbase + FA_AH + arow * 80 + acol * 2;
                asm volatile("ldmatrix.sync.aligned.m8n8.x4.shared.b16 {%0,%1,%2,%3},[%4];"
                             : "=r"(Af[0]), "=r"(Af[1]), "=r"(Af[2]), "=r"(Af[3]) : "r"(ad));
                #pragma unroll
                for (int ni = 0; ni < 4; ni++) MMA_F16(acc[mi][ni], Af, bf[ni]);
            }
        }
    }

    // Staged epilogue: single fp16 plane, coalesced 16B stores.
    __syncthreads();
    const int rb = wm * 64 + (lane >> 2);
    const int cb = wn * 32 + (lane & 3) * 2;
    #pragma unroll
    for (int ni = 0; ni < 4; ni++) {
        int c = cb + ni * 8;
        float b0 = bias[n0 + c], b1 = bias[n0 + c + 1];
        #pragma unroll
        for (int mi = 0; mi < 4; mi++) {
            #pragma unroll
            for (int h = 0; h < 2; h++) {
                int r = rb + mi * 16 + h * 8;
                *(__half2*)(smem_raw + r * 272 + c * 2) =
                    __floats2half2_rn(acc[mi][ni][h * 2 + 0] + b0,
                                      acc[mi][ni][h * 2 + 1] + b1);
            }
        }
    }
    __syncthreads();
    #pragma unroll
    for (int j = 0; j < 8; j++) {
        int f = j * 256 + tid;
        int r = f >> 4, ch = f & 15;
        uint4 v = *(const uint4*)(smem_raw + r * 272 + ch * 16);
        *(uint4*)(C16 + (size_t)(m0 + r) * N + n0 + ch * 8) = v;
    }
}

// ---------------------------------------------------------------------------
// Proj GEMM (1-term, 256 threads / 8 warps 2x4): A fp16 @ W fp16; fp32 out.
// smem per stage: A 10240 | B 8704 = 18944; 3 stages.
// ---------------------------------------------------------------------------
#define P_B  10240
#define P_ST 18944
#define P_NSTAGES 3
#define PROJ_DYNSMEM (P_NSTAGES * P_ST)

__global__ __launch_bounds__(256, 2)
void gemm_proj_kernel(const __half* __restrict__ A16,
                      const __half* __restrict__ B16,
                      float* __restrict__ C, int N, int K)
{
    extern __shared__ char smem_raw[];
    const uint32_t sbase = smem_u32(smem_raw);

    const int tid  = threadIdx.x;
    const int lane = tid & 31;
    const int warp = tid >> 5;
    const int wm   = warp >> 2;
    const int wn   = warp & 3;
    const int m0   = blockIdx.y * 128;
    const int n0   = blockIdx.x * 128;
    const int KT   = K / 32;

    float acc[4][4][4];
    #pragma unroll
    for (int mi = 0; mi < 4; mi++)
        #pragma unroll
        for (int ni = 0; ni < 4; ni++)
            #pragma unroll
            for (int c = 0; c < 4; c++) acc[mi][ni][c] = 0.0f;

    // A: 128 rows x 4 chunks = 512 / 256 = 2 each; B: 512 / 256 = 2 each
    uint32_t aso[2]; size_t ago[2];
    uint32_t bso[2]; size_t bgo[2];
    #pragma unroll
    for (int j = 0; j < 2; j++) {
        int idx = j * 256 + tid;
        int ar = idx >> 2, ac = idx & 3;
        aso[j] = (uint32_t)(ar * 80 + ac * 16);
        ago[j] = (size_t)ar * K + ac * 8;
        int br = idx >> 4, bc = idx & 15;
        bso[j] = (uint32_t)(br * 272 + bc * 16);
        bgo[j] = (size_t)br * N + bc * 8;
    }

    auto load_stage = [&](int kt, int st) {
        uint32_t b = sbase + st * P_ST;
        const __half* pa = A16 + (size_t)m0 * K + kt * 32;
        const __half* pb = B16 + (size_t)(kt * 32) * N + n0;
        #pragma unroll
        for (int j = 0; j < 2; j++) CP_ASYNC16(b + aso[j],       pa + ago[j]);
        #pragma unroll
        for (int j = 0; j < 2; j++) CP_ASYNC16(b + P_B + bso[j], pb + bgo[j]);
        CP_COMMIT();
    };

    load_stage(0, 0);
    load_stage(1, 1);

    int stage = 0;
    for (int kt = 0; kt < KT; kt++) {
        if (kt + 1 < KT) {
            asm volatile("cp.async.wait_group 1;" ::: "memory");
        } else {
            asm volatile("cp.async.wait_group 0;" ::: "memory");
        }
        __syncthreads();

        if (kt + 2 < KT) {
            int st2 = stage + 2; if (st2 >= P_NSTAGES) st2 -= P_NSTAGES;
            load_stage(kt + 2, st2);
        }

        const uint32_t b = sbase + stage * P_ST;
        #pragma unroll
        for (int kh = 0; kh < 2; kh++) {
            uint32_t bf[4][2];
            const int brow = kh * 16 + (lane & 15);
            #pragma unroll
            for (int ni = 0; ni < 4; ni++) {
                uint32_t ad = b + P_B + brow * 272 + (uint32_t)((wn * 32 + ni * 8) * 2);
                asm volatile("ldmatrix.sync.aligned.m8n8.x2.trans.shared.b16 {%0,%1},[%2];"
                             : "=r"(bf[ni][0]), "=r"(bf[ni][1]) : "r"(ad));
            }
            #pragma unroll
            for (int mi = 0; mi < 4; mi++) {
                const int arow = wm * 64 + mi * 16 + ((lane >> 3) & 1) * 8 + (lane & 7);
                const int acol = kh * 16 + (lane >> 4) * 8;
                uint32_t Af[4];
                uint32_t ad = b + arow * 80 + acol * 2;
                asm volatile("ldmatrix.sync.aligned.m8n8.x4.shared.b16 {%0,%1,%2,%3},[%4];"
                             : "=r"(Af[0]), "=r"(Af[1]), "=r"(Af[2]), "=r"(Af[3]) : "r"(ad));
                #pragma unroll
                for (int ni = 0; ni < 4; ni++) MMA_F16(acc[mi][ni], Af, bf[ni]);
            }
        }
        stage++; if (stage >= P_NSTAGES) stage = 0;
    }

    const int rbase = m0 + wm * 64 + (lane >> 2);
    const int cbase = n0 + wn * 32 + (lane & 3) * 2;
    #pragma unroll
    for (int ni = 0; ni < 4; ni++) {
        int c = cbase + ni * 8;
        #pragma unroll
        for (int mi = 0; mi < 4; mi++) {
            int r = rbase + mi * 16;
            *(float2*)(C + (size_t)r * N + c) =
                make_float2(acc[mi][ni][0], acc[mi][ni][1]);
            *(float2*)(C + (size_t)(r + 8) * N + c) =
                make_float2(acc[mi][ni][2], acc[mi][ni][3]);
        }
    }
}

// ---------------------------------------------------------------------------
// Attention: 2 heads per block (grid 1024 x 6), 256 threads.
// Warps 0-3 -> head0, warps 4-7 -> head0+1. 128B-contiguous cp.async loads.
// ---------------------------------------------------------------------------
__global__ __launch_bounds__(256)
void attn_tc_kernel(const __half* __restrict__ qkv,
                    __half* __restrict__ ao)
{
    __shared__ __half sQ[2][64][40];
    __shared__ __half sK[2][64][40];
    __shared__ __half sV[2][64][40];

    const int wx    = blockIdx.x;
    const int head0 = blockIdx.y * 2;
    const int b  = wx >> 6;
    const int wi = wx & 63;
    const int wh = wi >> 3;
    const int wc = wi & 7;
    const int tid  = threadIdx.x;
    const int lane = tid & 31;
    const int warp = tid >> 5;
    const int hg   = warp >> 2;     // head group 0/1
    const int wl   = warp & 3;      // warp-in-group

    // Loads: 3 mats x 64 tokens x 2 heads x 4 chunks = 1536 / 256 = 6 each.
    // Layout f = [m][r][h][c] -> 8 consecutive threads cover 128B contiguous.
    {
        uint32_t dst[3] = { smem_u32(&sQ[0][0][0]), smem_u32(&sK[0][0][0]),
                            smem_u32(&sV[0][0][0]) };
        #pragma unroll
        for (int j = 0; j < 6; j++) {
            int f = j * 256 + tid;
            int c = f & 3;
            int h = (f >> 2) & 1;
            int r = (f >> 3) & 63;
            int m = f >> 9;
            int n = ((wh * 8 + (r >> 3)) << 6) + wc * 8 + (r & 7);
            const __half* src = qkv + (size_t)(b * 4096 + n) * QKV_DIM
                                + m * 384 + (head0 + h) * 32 + c * 8;
            CP_ASYNC16(dst[m] + (uint32_t)(h * 5120 + r * 80 + c * 16), src);
        }
        CP_COMMIT();
    }
    asm volatile("cp.async.wait_group 0;" ::: "memory");
    __syncthreads();

    float cS[8][4];
    #pragma unroll
    for (int nt = 0; nt < 8; nt++)
        #pragma unroll
        for (int c = 0; c < 4; c++) cS[nt][c] = 0.0f;

    #pragma unroll
    for (int kt = 0; kt < 2; kt++) {
        const int arow = wl * 16 + ((lane >> 3) & 1) * 8 + (lane & 7);
        const int acol = kt * 16 + (lane >> 4) * 8;
        uint32_t qf[4];
        uint32_t ad = smem_u32(&sQ[hg][arow][acol]);
        asm volatile("ldmatrix.sync.aligned.m8n8.x4.shared.b16 {%0,%1,%2,%3},[%4];"
                     : "=r"(qf[0]), "=r"(qf[1]), "=r"(qf[2]), "=r"(qf[3]) : "r"(ad));
        #pragma unroll
        for (int nt = 0; nt < 8; nt++) {
            const int brow = nt * 8 + (lane & 7);
            const int bcol = kt * 16 + ((lane >> 3) & 1) * 8;
            uint32_t kf[2];
            uint32_t bd = smem_u32(&sK[hg][brow][bcol]);
            asm volatile("ldmatrix.sync.aligned.m8n8.x2.shared.b16 {%0,%1},[%2];"
                         : "=r"(kf[0]), "=r"(kf[1]) : "r"(bd));
            MMA_F16(cS[nt], qf, kf);
        }
    }

    const float scale = 0.17677669529663687f;
    {
        float m0 = -1e30f, m1 = -1e30f;
        #pragma unroll
        for (int nt = 0; nt < 8; nt++) {
            m0 = fmaxf(m0, fmaxf(cS[nt][0], cS[nt][1]));
            m1 = fmaxf(m1, fmaxf(cS[nt][2], cS[nt][3]));
        }
        m0 = fmaxf(m0, __shfl_xor_sync(0xffffffffu, m0, 1));
        m0 = fmaxf(m0, __shfl_xor_sync(0xffffffffu, m0, 2));
        m1 = fmaxf(m1, __shfl_xor_sync(0xffffffffu, m1, 1));
        m1 = fmaxf(m1, __shfl_xor_sync(0xffffffffu, m1, 2));
        float s0 = 0.f, s1 = 0.f;
        #pragma unroll
        for (int nt = 0; nt < 8; nt++) {
            cS[nt][0] = __expf((cS[nt][0] - m0) * scale); s0 += cS[nt][0];
            cS[nt][1] = __expf((cS[nt][1] - m0) * scale); s0 += cS[nt][1];
            cS[nt][2] = __expf((cS[nt][2] - m1) * scale); s1 += cS[nt][2];
            cS[nt][3] = __expf((cS[nt][3] - m1) * scale); s1 += cS[nt][3];
        }
        s0 += __shfl_xor_sync(0xffffffffu, s0, 1);
        s0 += __shfl_xor_sync(0xffffffffu, s0, 2);
        s1 += __shfl_xor_sync(0xffffffffu, s1, 1);
        s1 += __shfl_xor_sync(0xffffffffu, s1, 2);
        float i0 = 1.0f / s0, i1 = 1.0f / s1;
        #pragma unroll
        for (int nt = 0; nt < 8; nt++) {
            cS[nt][0] *= i0; cS[nt][1] *= i0;
            cS[nt][2] *= i1; cS[nt][3] *= i1;
        }
    }

    uint32_t pf[4][4];
    #pragma unroll
    for (int kt = 0; kt < 4; kt++) {
        #pragma unroll
        for (int half = 0; half < 2; half++) {
            int nt = 2 * kt + half;
            __half2 H0 = __floats2half2_rn(cS[nt][0], cS[nt][1]);
            __half2 H1 = __floats2half2_rn(cS[nt][2], cS[nt][3]);
            pf[kt][half * 2 + 0] = *(uint32_t*)&H0;
            pf[kt][half * 2 + 1] = *(uint32_t*)&H1;
        }
    }

    float cO[4][4];
    #pragma unroll
    for (int nt = 0; nt < 4; nt++)
        #pragma unroll
        for (int c = 0; c < 4; c++) cO[nt][c] = 0.0f;

    #pragma unroll
    for (int kt = 0; kt < 4; kt++) {
        const int vrow = kt * 16 + (lane & 15);
        #pragma unroll
        for (int nt = 0; nt < 4; nt++) {
            uint32_t vf[2];
            uint32_t ad = smem_u32(&sV[hg][vrow][nt * 8]);
            asm volatile("ldmatrix.sync.aligned.m8n8.x2.trans.shared.b16 {%0,%1},[%2];"
                         : "=r"(vf[0]), "=r"(vf[1]) : "r"(ad));
            MMA_F16(cO[nt], pf[kt], vf);
        }
    }

    // Stage output into sQ[hg], then 128B-contiguous stores.
    __syncthreads();
    {
        const int g0 = lane >> 2;
        const int c2 = (lane & 3) * 2;
        #pragma unroll
        for (int half = 0; half < 2; half++) {
            int r = wl * 16 + g0 + half * 8;
            #pragma unroll
            for (int nt = 0; nt < 4; nt++) {
                *(__half2*)&sQ[hg][r][nt * 8 + c2] =
                    __floats2half2_rn(cO[nt][half * 2 + 0], cO[nt][half * 2 + 1]);
            }
        }
    }
    __syncthreads();
    {
        // 2 heads x 64 tokens x 4 chunks = 512 / 256 = 2 each
        #pragma unroll
        for (int j = 0; j < 2; j++) {
            int f = j * 256 + tid;
            int c = f & 3;
            int h = (f >> 2) & 1;
            int r = f >> 3;
            int n = ((wh * 8 + (r >> 3)) << 6) + wc * 8 + (r & 7);
            size_t base = (size_t)(b * 4096 + n) * C_DIM + (head0 + h) * 32 + c * 8;
            *(uint4*)(ao + base) = *(const uint4*)&sQ[h][r][c * 8];
        }
    }
}

// ---------------------------------------------------------------------------
// Host launcher
// ---------------------------------------------------------------------------
extern "C" void kernel_launch(void* const* d_in, const int* in_sizes, int n_in,
                              void* d_out, int out_size)
{
    const float* x      = (const float*)d_in[0];
    const float* W_qkv  = (const float*)d_in[1];
    const float* b_qkv  = (const float*)d_in[2];
    const float* W_proj = (const float*)d_in[3];
    float* out = (float*)d_out;

    __half *qkv, *ao, *wq, *wp;
    cudaGetSymbolAddress((void**)&qkv, g_qkv);
    cudaGetSymbolAddress((void**)&ao,  g_ao);
    cudaGetSymbolAddress((void**)&wq,  g_wq);
    cudaGetSymbolAddress((void**)&wp,  g_wp);

    cudaFuncSetAttribute(gemm_qkv_kernel,
                         cudaFuncAttributeMaxDynamicSharedMemorySize, FA_DYNSMEM);
    cudaFuncSetAttribute(gemm_proj_kernel,
                         cudaFuncAttributeMaxDynamicSharedMemorySize, PROJ_DYNSMEM);

    {
        int w4 = C_DIM * QKV_DIM / 4;
        convert_kernel<<<(w4 + 255) / 256, 256>>>(W_qkv, wq, w4);
        int p4 = C_DIM * C_DIM / 4;
        convert_kernel<<<(p4 + 255) / 256, 256>>>(W_proj, wp, p4);
    }
    {
        dim3 grid(QKV_DIM / 128, TOKENS / 128);
        gemm_qkv_kernel<<<grid, 256, FA_DYNSMEM>>>(x, wq, b_qkv, qkv,
                                                   QKV_DIM, C_DIM);
    }
    {
        dim3 grid(1024, 6);
        attn_tc_kernel<<<grid, 256>>>(qkv, ao);
    }
    {
        dim3 grid(C_DIM / 128, TOKENS / 128);
        gemm_proj_kernel<<<grid, 256, PROJ_DYNSMEM>>>(ao, wp, out, C_DIM, C_DIM);
    }
}

// round 17
// speedup vs baseline: 1.0201x; 1.0201x over previous
#include <cuda_runtime.h>
#include <cuda_fp16.h>
#include <cstdint>

// x: [16,4096,384] fp32 -> out [16,4096,384] fp32
// 8x8 window attention over 64x64 grid, 12 heads, hd=32.
// fp16 1-term everywhere (R15 config); merged weight-convert launch.

#define TOKENS   65536
#define C_DIM    384
#define QKV_DIM  1152

__device__ __half  g_qkv[(size_t)TOKENS * QKV_DIM];
__device__ __half  g_ao [(size_t)TOKENS * C_DIM];
__device__ __half  g_wq [(size_t)C_DIM * QKV_DIM];
__device__ __half  g_wp [(size_t)C_DIM * C_DIM];

static __device__ __forceinline__ uint32_t smem_u32(const void* p) {
    return (uint32_t)__cvta_generic_to_shared(p);
}

#define CP_ASYNC16(smem, gptr) \
    asm volatile("cp.async.cg.shared.global [%0], [%1], 16;" :: "r"(smem), "l"(gptr))
#define CP_COMMIT() asm volatile("cp.async.commit_group;" ::: "memory")

#define MMA_F16(d, a, b)                                                       \
    asm volatile(                                                              \
        "mma.sync.aligned.m16n8k16.row.col.f32.f16.f16.f32 "                   \
        "{%0,%1,%2,%3},{%4,%5,%6,%7},{%8,%9},{%0,%1,%2,%3};"                   \
        : "+f"(d[0]), "+f"(d[1]), "+f"(d[2]), "+f"(d[3])                       \
        : "r"(a[0]), "r"(a[1]), "r"(a[2]), "r"(a[3]), "r"(b[0]), "r"(b[1]))

// ---------------------------------------------------------------------------
// Merged fp32 -> fp16 convert for BOTH weight matrices (one launch).
// ---------------------------------------------------------------------------
__global__ void convert2_kernel(const float* __restrict__ a,
                                __half* __restrict__ oa, int na4,
                                const float* __restrict__ b,
                                __half* __restrict__ ob, int nb4)
{
    int i = blockIdx.x * blockDim.x + threadIdx.x;
    const float* in; __half* out16; int idx;
    if (i < na4)            { in = a; out16 = oa; idx = i; }
    else if (i < na4 + nb4) { in = b; out16 = ob; idx = i - na4; }
    else return;
    float4 v = ((const float4*)in)[idx];
    __half2* op = (__half2*)out16;
    op[idx*2]   = __floats2half2_rn(v.x, v.y);
    op[idx*2+1] = __floats2half2_rn(v.z, v.w);
}

// ---------------------------------------------------------------------------
// QKV GEMM (1-term, 128 thr / 4 warps 2x2, warp 64x64): A fp32 -> fp16
// in-kernel; C = A16 @ W16 + bias; fp16 out (staged coalesced stores).
// smem: AF32 2x18432 @0 | AH 10240 @36864 | B 2x8704 @47104  (=64512)
// ---------------------------------------------------------------------------
#define FA_AF32    0
#define FA_AF32_ST 18432
#define FA_AH      36864
#define FA_B       47104
#define FA_B_ST    8704
#define FA_DYNSMEM 64512

__global__ __launch_bounds__(128, 2)
void gemm_qkv_kernel(const float* __restrict__ A,
                     const __half* __restrict__ B16,
                     const float* __restrict__ bias,
                     __half* __restrict__ C16, int N, int K)
{
    extern __shared__ char smem_raw[];
    const uint32_t sbase = smem_u32(smem_raw);

    const int tid  = threadIdx.x;
    const int lane = tid & 31;
    const int warp = tid >> 5;
    const int wm   = warp >> 1;
    const int wn   = warp & 1;
    const int m0   = blockIdx.y * 128;
    const int n0   = blockIdx.x * 128;
    const int KT   = K / 32;

    float acc[4][8][4];
    #pragma unroll
    for (int mi = 0; mi < 4; mi++)
        #pragma unroll
        for (int ni = 0; ni < 8; ni++)
            #pragma unroll
            for (int c = 0; c < 4; c++) acc[mi][ni][c] = 0.0f;

    uint32_t afo[8]; size_t afg[8];
    #pragma unroll
    for (int j = 0; j < 8; j++) {
        int idx = j * 128 + tid;
        int r = idx >> 3, c = idx & 7;
        afo[j] = (uint32_t)(r * 144 + c * 16);
        afg[j] = (size_t)r * K + c * 4;
    }
    uint32_t bso[4]; size_t bgo[4];
    #pragma unroll
    for (int j = 0; j < 4; j++) {
        int idx = j * 128 + tid;
        int br = idx >> 4, bc = idx & 15;
        bso[j] = (uint32_t)(br * 272 + bc * 16);
        bgo[j] = (size_t)br * N + bc * 8;
    }

    auto load_stage = [&](int kt, int st) {
        uint32_t ab = sbase + FA_AF32 + st * FA_AF32_ST;
        const float* pa = A + (size_t)m0 * K + kt * 32;
        #pragma unroll
        for (int j = 0; j < 8; j++) CP_ASYNC16(ab + afo[j], pa + afg[j]);
        uint32_t bb = sbase + FA_B + st * FA_B_ST;
        const __half* pb = B16 + (size_t)(kt * 32) * N + n0;
        #pragma unroll
        for (int j = 0; j < 4; j++) CP_ASYNC16(bb + bso[j], pb + bgo[j]);
        CP_COMMIT();
    };

    load_stage(0, 0);

    for (int kt = 0; kt < KT; kt++) {
        const int st = kt & 1;
        asm volatile("cp.async.wait_group 0;" ::: "memory");
        __syncthreads();

        if (kt + 1 < KT) load_stage(kt + 1, st ^ 1);

        {
            const float* arow = (const float*)(smem_raw + FA_AF32 + st * FA_AF32_ST
                                               + tid * 144);
            __half* hrow = (__half*)(smem_raw + FA_AH + tid * 80);
            #pragma unroll
            for (int j = 0; j < 8; j++) {
                float4 v = *(const float4*)(arow + j * 4);
                *(__half2*)(hrow + j * 4)     = __floats2half2_rn(v.x, v.y);
                *(__half2*)(hrow + j * 4 + 2) = __floats2half2_rn(v.z, v.w);
            }
        }
        __syncthreads();

        const uint32_t bb = sbase + FA_B + st * FA_B_ST;
        #pragma unroll
        for (int kh = 0; kh < 2; kh++) {
            uint32_t bf[8][2];
            const int brow = kh * 16 + (lane & 15);
            #pragma unroll
            for (int ni = 0; ni < 8; ni++) {
                uint32_t ad = bb + brow * 272 + (uint32_t)((wn * 64 + ni * 8) * 2);
                asm volatile("ldmatrix.sync.aligned.m8n8.x2.trans.shared.b16 {%0,%1},[%2];"
                             : "=r"(bf[ni][0]), "=r"(bf[ni][1]) : "r"(ad));
            }
            #pragma unroll
            for (int mi = 0; mi < 4; mi++) {
                const int arow = wm * 64 + mi * 16 + ((lane >> 3) & 1) * 8 + (lane & 7);
                const int acol = kh * 16 + (lane >> 4) * 8;
                uint32_t Af[4];
                uint32_t ad = sbase + FA_AH + arow * 80 + acol * 2;
                asm volatile("ldmatrix.sync.aligned.m8n8.x4.shared.b16 {%0,%1,%2,%3},[%4];"
                             : "=r"(Af[0]), "=r"(Af[1]), "=r"(Af[2]), "=r"(Af[3]) : "r"(ad));
                #pragma unroll
                for (int ni = 0; ni < 8; ni++) MMA_F16(acc[mi][ni], Af, bf[ni]);
            }
        }
    }

    __syncthreads();
    const int rb = wm * 64 + (lane >> 2);
    const int cb = wn * 64 + (lane & 3) * 2;
    #pragma unroll
    for (int ni = 0; ni < 8; ni++) {
        int c = cb + ni * 8;
        float b0 = bias[n0 + c], b1 = bias[n0 + c + 1];
        #pragma unroll
        for (int mi = 0; mi < 4; mi++) {
            #pragma unroll
            for (int h = 0; h < 2; h++) {
                int r = rb + mi * 16 + h * 8;
                *(__half2*)(smem_raw + r * 272 + c * 2) =
                    __floats2half2_rn(acc[mi][ni][h * 2 + 0] + b0,
                                      acc[mi][ni][h * 2 + 1] + b1);
            }
        }
    }
    __syncthreads();
    #pragma unroll
    for (int j = 0; j < 16; j++) {
        int f = j * 128 + tid;
        int r = f >> 4, ch = f & 15;
        uint4 v = *(const uint4*)(smem_raw + r * 272 + ch * 16);
        *(uint4*)(C16 + (size_t)(m0 + r) * N + n0 + ch * 8) = v;
    }
}

// ---------------------------------------------------------------------------
// Proj GEMM (1-term, 128 thr): A fp16 @ W fp16; fp32 out. R15 version.
// ---------------------------------------------------------------------------
#define P_B  10240
#define P_ST 18944
#define P_NSTAGES 3
#define PROJ_DYNSMEM (P_NSTAGES * P_ST)

__global__ __launch_bounds__(128, 2)
void gemm_proj_kernel(const __half* __restrict__ A16,
                      const __half* __restrict__ B16,
                      float* __restrict__ C, int N, int K)
{
    extern __shared__ char smem_raw[];
    const uint32_t sbase = smem_u32(smem_raw);

    const int tid  = threadIdx.x;
    const int lane = tid & 31;
    const int warp = tid >> 5;
    const int wm   = warp >> 1;
    const int wn   = warp & 1;
    const int m0   = blockIdx.y * 128;
    const int n0   = blockIdx.x * 128;
    const int KT   = K / 32;

    float acc[4][8][4];
    #pragma unroll
    for (int mi = 0; mi < 4; mi++)
        #pragma unroll
        for (int ni = 0; ni < 8; ni++)
            #pragma unroll
            for (int c = 0; c < 4; c++) acc[mi][ni][c] = 0.0f;

    uint32_t aso[4]; size_t ago[4];
    uint32_t bso[4]; size_t bgo[4];
    #pragma unroll
    for (int j = 0; j < 4; j++) {
        int idx = j * 128 + tid;
        int ar = idx >> 2, ac = idx & 3;
        aso[j] = (uint32_t)(ar * 80 + ac * 16);
        ago[j] = (size_t)ar * K + ac * 8;
        int br = idx >> 4, bc = idx & 15;
        bso[j] = (uint32_t)(br * 272 + bc * 16);
        bgo[j] = (size_t)br * N + bc * 8;
    }

    auto load_stage = [&](int kt, int st) {
        uint32_t b = sbase + st * P_ST;
        const __half* pa = A16 + (size_t)m0 * K + kt * 32;
        const __half* pb = B16 + (size_t)(kt * 32) * N + n0;
        #pragma unroll
        for (int j = 0; j < 4; j++) CP_ASYNC16(b + aso[j],       pa + ago[j]);
        #pragma unroll
        for (int j = 0; j < 4; j++) CP_ASYNC16(b + P_B + bso[j], pb + bgo[j]);
        CP_COMMIT();
    };

    load_stage(0, 0);
    load_stage(1, 1);

    int stage = 0;
    for (int kt = 0; kt < KT; kt++) {
        if (kt + 1 < KT) {
            asm volatile("cp.async.wait_group 1;" ::: "memory");
        } else {
            asm volatile("cp.async.wait_group 0;" ::: "memory");
        }
        __syncthreads();

        if (kt + 2 < KT) {
            int st2 = stage + 2; if (st2 >= P_NSTAGES) st2 -= P_NSTAGES;
            load_stage(kt + 2, st2);
        }

        const uint32_t b = sbase + stage * P_ST;
        #pragma unroll
        for (int kh = 0; kh < 2; kh++) {
            uint32_t bf[8][2];
            const int brow = kh * 16 + (lane & 15);
            #pragma unroll
            for (int ni = 0; ni < 8; ni++) {
                uint32_t ad = b + P_B + brow * 272 + (uint32_t)((wn * 64 + ni * 8) * 2);
                asm volatile("ldmatrix.sync.aligned.m8n8.x2.trans.shared.b16 {%0,%1},[%2];"
                             : "=r"(bf[ni][0]), "=r"(bf[ni][1]) : "r"(ad));
            }
            #pragma unroll
            for (int mi = 0; mi < 4; mi++) {
                const int arow = wm * 64 + mi * 16 + ((lane >> 3) & 1) * 8 + (lane & 7);
                const int acol = kh * 16 + (lane >> 4) * 8;
                uint32_t Af[4];
                uint32_t ad = b + arow * 80 + acol * 2;
                asm volatile("ldmatrix.sync.aligned.m8n8.x4.shared.b16 {%0,%1,%2,%3},[%4];"
                             : "=r"(Af[0]), "=r"(Af[1]), "=r"(Af[2]), "=r"(Af[3]) : "r"(ad));
                #pragma unroll
                for (int ni = 0; ni < 8; ni++) MMA_F16(acc[mi][ni], Af, bf[ni]);
            }
        }
        stage++; if (stage >= P_NSTAGES) stage = 0;
    }

    const int rbase = m0 + wm * 64 + (lane >> 2);
    const int cbase = n0 + wn * 64 + (lane & 3) * 2;
    #pragma unroll
    for (int ni = 0; ni < 8; ni++) {
        int c = cbase + ni * 8;
        #pragma unroll
        for (int mi = 0; mi < 4; mi++) {
            int r = rbase + mi * 16;
            *(float2*)(C + (size_t)r * N + c) =
                make_float2(acc[mi][ni][0], acc[mi][ni][1]);
            *(float2*)(C + (size_t)(r + 8) * N + c) =
                make_float2(acc[mi][ni][2], acc[mi][ni][3]);
        }
    }
}

// ---------------------------------------------------------------------------
// Attention: single fp16 qkv plane, 1-term QK and PV. R15 version.
// ---------------------------------------------------------------------------
__global__ __launch_bounds__(128)
void attn_tc_kernel(const __half* __restrict__ qkv,
                    __half* __restrict__ ao)
{
    __shared__ __half sQ[64][40];
    __shared__ __half sK[64][40];
    __shared__ __half sV[64][40];

    const int wx   = blockIdx.x;
    const int head = blockIdx.y;
    const int b  = wx >> 6;
    const int wi = wx & 63;
    const int wh = wi >> 3;
    const int wc = wi & 7;
    const int tid  = threadIdx.x;
    const int lane = tid & 31;
    const int warp = tid >> 5;

    {
        uint32_t dst[3] = { smem_u32(&sQ[0][0]), smem_u32(&sK[0][0]),
                            smem_u32(&sV[0][0]) };
        #pragma unroll
        for (int j = 0; j < 6; j++) {
            int f = j * 128 + tid;
            int m = f >> 8;
            int q = f & 255;
            int r = q >> 2;
            int c = q & 3;
            int n = ((wh * 8 + (r >> 3)) << 6) + wc * 8 + (r & 7);
            const __half* src = qkv
                + (size_t)(b * 4096 + n) * QKV_DIM + m * 384 + head * 32 + c * 8;
            CP_ASYNC16(dst[m] + (uint32_t)(r * 80 + c * 16), src);
        }
        CP_COMMIT();
    }
    asm volatile("cp.async.wait_group 0;" ::: "memory");
    __syncthreads();

    float cS[8][4];
    #pragma unroll
    for (int nt = 0; nt < 8; nt++)
        #pragma unroll
        for (int c = 0; c < 4; c++) cS[nt][c] = 0.0f;

    #pragma unroll
    for (int kt = 0; kt < 2; kt++) {
        const int arow = warp * 16 + ((lane >> 3) & 1) * 8 + (lane & 7);
        const int acol = kt * 16 + (lane >> 4) * 8;
        uint32_t qf[4];
        uint32_t ad = smem_u32(&sQ[arow][acol]);
        asm volatile("ldmatrix.sync.aligned.m8n8.x4.shared.b16 {%0,%1,%2,%3},[%4];"
                     : "=r"(qf[0]), "=r"(qf[1]), "=r"(qf[2]), "=r"(qf[3]) : "r"(ad));
        #pragma unroll
        for (int nt = 0; nt < 8; nt++) {
            const int brow = nt * 8 + (lane & 7);
            const int bcol = kt * 16 + ((lane >> 3) & 1) * 8;
            uint32_t kf[2];
            uint32_t bd = smem_u32(&sK[brow][bcol]);
            asm volatile("ldmatrix.sync.aligned.m8n8.x2.shared.b16 {%0,%1},[%2];"
                         : "=r"(kf[0]), "=r"(kf[1]) : "r"(bd));
            MMA_F16(cS[nt], qf, kf);
        }
    }

    const float scale = 0.17677669529663687f;
    {
        float m0 = -1e30f, m1 = -1e30f;
        #pragma unroll
        for (int nt = 0; nt < 8; nt++) {
            m0 = fmaxf(m0, fmaxf(cS[nt][0], cS[nt][1]));
            m1 = fmaxf(m1, fmaxf(cS[nt][2], cS[nt][3]));
        }
        m0 = fmaxf(m0, __shfl_xor_sync(0xffffffffu, m0, 1));
        m0 = fmaxf(m0, __shfl_xor_sync(0xffffffffu, m0, 2));
        m1 = fmaxf(m1, __shfl_xor_sync(0xffffffffu, m1, 1));
        m1 = fmaxf(m1, __shfl_xor_sync(0xffffffffu, m1, 2));
        float s0 = 0.f, s1 = 0.f;
        #pragma unroll
        for (int nt = 0; nt < 8; nt++) {
            cS[nt][0] = __expf((cS[nt][0] - m0) * scale); s0 += cS[nt][0];
            cS[nt][1] = __expf((cS[nt][1] - m0) * scale); s0 += cS[nt][1];
            cS[nt][2] = __expf((cS[nt][2] - m1) * scale); s1 += cS[nt][2];
            cS[nt][3] = __expf((cS[nt][3] - m1) * scale); s1 += cS[nt][3];
        }
        s0 += __shfl_xor_sync(0xffffffffu, s0, 1);
        s0 += __shfl_xor_sync(0xffffffffu, s0, 2);
        s1 += __shfl_xor_sync(0xffffffffu, s1, 1);
        s1 += __shfl_xor_sync(0xffffffffu, s1, 2);
        float i0 = 1.0f / s0, i1 = 1.0f / s1;
        #pragma unroll
        for (int nt = 0; nt < 8; nt++) {
            cS[nt][0] *= i0; cS[nt][1] *= i0;
            cS[nt][2] *= i1; cS[nt][3] *= i1;
        }
    }

    uint32_t pf[4][4];
    #pragma unroll
    for (int kt = 0; kt < 4; kt++) {
        #pragma unroll
        for (int half = 0; half < 2; half++) {
            int nt = 2 * kt + half;
            __half2 H0 = __floats2half2_rn(cS[nt][0], cS[nt][1]);
            __half2 H1 = __floats2half2_rn(cS[nt][2], cS[nt][3]);
            pf[kt][half * 2 + 0] = *(uint32_t*)&H0;
            pf[kt][half * 2 + 1] = *(uint32_t*)&H1;
        }
    }

    float cO[4][4];
    #pragma unroll
    for (int nt = 0; nt < 4; nt++)
        #pragma unroll
        for (int c = 0; c < 4; c++) cO[nt][c] = 0.0f;

    #pragma unroll
    for (int kt = 0; kt < 4; kt++) {
        const int vrow = kt * 16 + (lane & 15);
        #pragma unroll
        for (int nt = 0; nt < 4; nt++) {
            uint32_t vf[2];
            uint32_t ad = smem_u32(&sV[vrow][nt * 8]);
            asm volatile("ldmatrix.sync.aligned.m8n8.x2.trans.shared.b16 {%0,%1},[%2];"
                         : "=r"(vf[0]), "=r"(vf[1]) : "r"(ad));
            MMA_F16(cO[nt], pf[kt], vf);
        }
    }

    __syncthreads();
    {
        const int g0 = lane >> 2;
        const int c2 = (lane & 3) * 2;
        #pragma unroll
        for (int half = 0; half < 2; half++) {
            int r = warp * 16 + g0 + half * 8;
            #pragma unroll
            for (int nt = 0; nt < 4; nt++) {
                *(__half2*)&sQ[r][nt * 8 + c2] =
                    __floats2half2_rn(cO[nt][half * 2 + 0], cO[nt][half * 2 + 1]);
            }
        }
    }
    __syncthreads();
    {
        #pragma unroll
        for (int j = 0; j < 2; j++) {
            int f = j * 128 + tid;
            int r = f >> 2;
            int ch = f & 3;
            int n = ((wh * 8 + (r >> 3)) << 6) + wc * 8 + (r & 7);
            size_t base = (size_t)(b * 4096 + n) * C_DIM + head * 32 + ch * 8;
            *(uint4*)(ao + base) = *(const uint4*)&sQ[r][ch * 8];
        }
    }
}

// ---------------------------------------------------------------------------
// Host launcher (4 launches)
// ---------------------------------------------------------------------------
extern "C" void kernel_launch(void* const* d_in, const int* in_sizes, int n_in,
                              void* d_out, int out_size)
{
    const float* x      = (const float*)d_in[0];
    const float* W_qkv  = (const float*)d_in[1];
    const float* b_qkv  = (const float*)d_in[2];
    const float* W_proj = (const float*)d_in[3];
    float* out = (float*)d_out;

    __half *qkv, *ao, *wq, *wp;
    cudaGetSymbolAddress((void**)&qkv, g_qkv);
    cudaGetSymbolAddress((void**)&ao,  g_ao);
    cudaGetSymbolAddress((void**)&wq,  g_wq);
    cudaGetSymbolAddress((void**)&wp,  g_wp);

    cudaFuncSetAttribute(gemm_qkv_kernel,
                         cudaFuncAttributeMaxDynamicSharedMemorySize, FA_DYNSMEM);
    cudaFuncSetAttribute(gemm_proj_kernel,
                         cudaFuncAttributeMaxDynamicSharedMemorySize, PROJ_DYNSMEM);

    // Merged weight converts: one launch for both matrices.
    {
        int w4 = C_DIM * QKV_DIM / 4;
        int p4 = C_DIM * C_DIM / 4;
        int tot = w4 + p4;
        convert2_kernel<<<(tot + 255) / 256, 256>>>(W_qkv, wq, w4, W_proj, wp, p4);
    }
    {
        dim3 grid(QKV_DIM / 128, TOKENS / 128);
        gemm_qkv_kernel<<<grid, 128, FA_DYNSMEM>>>(x, wq, b_qkv, qkv,
                                                   QKV_DIM, C_DIM);
    }
    {
        dim3 grid(1024, 12);
        attn_tc_kernel<<<grid, 128>>>(qkv, ao);
    }
    {
        dim3 grid(C_DIM / 128, TOKENS / 128);
        gemm_proj_kernel<<<grid, 128, PROJ_DYNSMEM>>>(ao, wp, out, C_DIM, C_DIM);
    }
}